// round 9
// baseline (speedup 1.0000x reference)
#include <cuda_runtime.h>
#include <cuda_bf16.h>
#include <cstdint>

// ---------------------------------------------------------------------------
// BVP Helmholtz residual via 2nd-order jet propagation on mma.sync bf16 HMMA
// (3-pass hi/lo split). Round 9 = round 8 + pass-outer MMA ordering: all A/B
// fragments for a k=16 sub-step loaded first, then 3 passes of 16 independent
// MMAs each -> accumulator reuse distance 16 (throughput-bound, not
// latency-bound).
// ---------------------------------------------------------------------------

#define HD 256
#define SB 24          // samples per CTA
#define AROW 1040      // A row bytes: hi[0,512) pad lo[528,1040)  == D row
#define BROW 80        // B stage row stride bytes
#define BSPLIT 20480   // 256*80
#define BBUF 40960     // 2 splits
#define DROW 260       // D row stride in floats (= 1040 B)

#define A_OFF 0
#define B_OFF 133120   // 128*1040
#define XYZF_OFF 215040
#define PART_OFF 215424
#define SMEM_BYTES 218624

// prepped weights: [layer][split hi/lo][n][k] bf16
__device__ __align__(16) __nv_bfloat16 Wbf[2][2][HD][HD];

__global__ __launch_bounds__(256)
void prep_weights(const float* __restrict__ W2, const float* __restrict__ W3)
{
    int t = blockIdx.x * 256 + threadIdx.x;      // 131072
    int layer = t >> 16, n = (t >> 8) & 255, k = t & 255;
    float w = (layer ? W3 : W2)[n * HD + k];
    __nv_bfloat16 h = __float2bfloat16(w);
    __nv_bfloat16 l = __float2bfloat16(w - __bfloat162float(h));
    Wbf[layer][0][n][k] = h;
    Wbf[layer][1][n][k] = l;
}

__device__ __forceinline__ uint32_t smem_u32(const void* p) {
    uint32_t a;
    asm("{ .reg .u64 t; cvta.to.shared.u64 t, %1; cvt.u32.u64 %0, t; }"
        : "=r"(a) : "l"(p));
    return a;
}
__device__ __forceinline__ void ldsm4(uint32_t* r, uint32_t a) {
    asm volatile("ldmatrix.sync.aligned.m8n8.x4.shared.b16 {%0,%1,%2,%3}, [%4];"
                 : "=r"(r[0]), "=r"(r[1]), "=r"(r[2]), "=r"(r[3]) : "r"(a));
}
__device__ __forceinline__ void ldsm2(uint32_t* r, uint32_t a) {
    asm volatile("ldmatrix.sync.aligned.m8n8.x2.shared.b16 {%0,%1}, [%2];"
                 : "=r"(r[0]), "=r"(r[1]) : "r"(a));
}
__device__ __forceinline__ void mma_bf16(float* c, const uint32_t* a,
                                         const uint32_t* b) {
    asm volatile("mma.sync.aligned.m16n8k16.row.col.f32.bf16.bf16.f32 "
                 "{%0,%1,%2,%3}, {%4,%5,%6,%7}, {%8,%9}, {%0,%1,%2,%3};"
                 : "+f"(c[0]), "+f"(c[1]), "+f"(c[2]), "+f"(c[3])
                 : "r"(a[0]), "r"(a[1]), "r"(a[2]), "r"(a[3]),
                   "r"(b[0]), "r"(b[1]));
}
__device__ __forceinline__ void cp16(uint32_t sa, const void* ga) {
    asm volatile("cp.async.cg.shared.global [%0], [%1], 16;"
                 :: "r"(sa), "l"(__cvta_generic_to_global(ga)) : "memory");
}
#define CP_COMMIT() asm volatile("cp.async.commit_group;" ::: "memory")
#define CP_WAIT(n)  asm volatile("cp.async.wait_group %0;" :: "n"(n) : "memory")

// fast tanh: 1 - 2/(exp(2u)+1). abs err ~3e-7.
__device__ __forceinline__ float ftanh(float u) {
    float e = __expf(2.0f * u);
    return 1.0f - __fdividef(2.0f, e + 1.0f);
}

__global__ __launch_bounds__(512, 1)
void bvp_mma_kernel(const float* __restrict__ gx, const float* __restrict__ gy,
                    const float* __restrict__ gz, const float* __restrict__ gf,
                    const float* __restrict__ W1, const float* __restrict__ b1,
                    const float* __restrict__ b2, const float* __restrict__ b3,
                    const float* __restrict__ W4, const float* __restrict__ b4,
                    float* __restrict__ out, int N)
{
    extern __shared__ char sm[];
    const uint32_t smb = smem_u32(sm);
    float* Dst  = (float*)(sm + A_OFF);       // aliases A region, row-for-row
    float* xyzf = (float*)(sm + XYZF_OFF);
    float* part = (float*)(sm + PART_OFF);    // [24][8][4]

    const int tid = threadIdx.x;
    const int wid = tid >> 5;
    const int lid = tid & 31;
    const int mg  = wid >> 3;                 // m-group 0/1 (rows mg*64..+64)
    const int ng  = wid & 7;                  // n-slice (cols ng*32..+32)
    const int n0w = ng << 5;
    const int n0  = blockIdx.x * SB;

    const float CX = (float)((0.5 * 0.6) * (0.5 * 0.6));
    const float CY = (float)((0.7 * 0.6) * (0.7 * 0.6));
    const float CZ = (float)((0.7 * 0.5) * (0.7 * 0.5));

    auto issue_stage = [&](int L, int kc, int buf) {
        #pragma unroll
        for (int j = 0; j < 4; ++j) {
            int i = tid + (j << 9);              // 0..2047
            int split = i >> 10;
            int n = (i >> 2) & 255;
            int seg = i & 3;
            uint32_t sa = smb + B_OFF + buf * BBUF + split * BSPLIT +
                          n * BROW + seg * 16;
            cp16(sa, &Wbf[L][split][n][kc * 32 + seg * 8]);
        }
        CP_COMMIT();
    };

    auto storeA = [&](int m, int k, float v) {
        __nv_bfloat16 h = __float2bfloat16(v);
        __nv_bfloat16 l = __float2bfloat16(v - __bfloat162float(h));
        char* base = sm + A_OFF + m * AROW + k * 2;
        *(__nv_bfloat16*)(base)       = h;
        *(__nv_bfloat16*)(base + 528) = l;
    };

    // prefetch first B stage of layer 0
    issue_stage(0, 0, 0);

    // coords
    if (tid < 96) {
        int ss = tid >> 2, w = tid & 3;
        int n = n0 + ss; if (n >= N) n = N - 1;
        const float* p = (w == 0) ? gx : (w == 1) ? gy : (w == 2) ? gz : gf;
        xyzf[tid] = p[n];
    }
    __syncthreads();

    // ---- layer 1: 4 -> 256, jets analytically ------------------------------
    #pragma unroll 1
    for (int it = 0; it < 12; ++it) {
        int idx = tid + (it << 9);               // 24*256 = 6144 items
        int s = idx >> 8, k = idx & 255;
        float4 w = *(const float4*)(W1 + k * 4);
        float u = fmaf(w.x, xyzf[s * 4 + 0], fmaf(w.y, xyzf[s * 4 + 1],
                  fmaf(w.z, xyzf[s * 4 + 2], fmaf(w.w, xyzf[s * 4 + 3],
                  b1[k]))));
        float yv = ftanh(u);
        float sg = fmaf(-yv, yv, 1.0f);
        float g  = CX * w.x * w.x + CY * w.y * w.y + CZ * w.z * w.z;
        int m = s * 5;
        storeA(m + 0, k, yv);
        storeA(m + 1, k, sg * w.x);
        storeA(m + 2, k, sg * w.y);
        storeA(m + 3, k, sg * w.z);
        storeA(m + 4, k, -2.0f * yv * sg * g);
    }

    const int g = lid >> 2, cc = (lid & 3) << 1;

    // ---- hidden layers 2,3 --------------------------------------------------
    #pragma unroll 1
    for (int L = 0; L < 2; ++L) {
        float acc[4][4][4];
        #pragma unroll
        for (int mt = 0; mt < 4; ++mt)
            #pragma unroll
            for (int nt = 0; nt < 4; ++nt)
                #pragma unroll
                for (int r = 0; r < 4; ++r) acc[mt][nt][r] = 0.f;

        #pragma unroll 1
        for (int kc = 0; kc < 8; ++kc) {
            int gi = L * 8 + kc;
            CP_WAIT(0);
            __syncthreads();   // stage gi ready everywhere; all warps are past
                               // chunk gi-1's reads of buffer (gi+1)&1
            if (gi + 1 < 16) {
                int nl = (gi + 1) >> 3, nkc = (gi + 1) & 7;
                issue_stage(nl, nkc, (gi + 1) & 1);
            }
            int buf = gi & 1;

            #pragma unroll
            for (int ks = 0; ks < 2; ++ks) {
                int kl0 = ks << 4;
                // --- load ALL fragments for this k=16 sub-step --------------
                uint32_t bf[2][4][2];
                #pragma unroll
                for (int nt = 0; nt < 4; ++nt) {
                    uint32_t ba = smb + B_OFF + buf * BBUF +
                                  (n0w + (nt << 3) + (lid & 7)) * BROW +
                                  (kl0 + (lid & 8)) * 2;
                    ldsm2(bf[0][nt], ba);
                    ldsm2(bf[1][nt], ba + BSPLIT);
                }
                uint32_t ah[4][4], al[4][4];
                #pragma unroll
                for (int mt = 0; mt < 4; ++mt) {
                    int row = (mg << 6) + (mt << 4) + (lid & 15);
                    uint32_t aa = smb + A_OFF + row * AROW +
                                  (kc * 32 + kl0 + ((lid >> 4) << 3)) * 2;
                    ldsm4(ah[mt], aa);
                    ldsm4(al[mt], aa + 528);
                }
                // --- pass-outer MMA: 16 independent accs per pass -----------
                #pragma unroll
                for (int mt = 0; mt < 4; ++mt)
                    #pragma unroll
                    for (int nt = 0; nt < 4; ++nt)
                        mma_bf16(acc[mt][nt], ah[mt], bf[0][nt]);  // hi*hi
                #pragma unroll
                for (int mt = 0; mt < 4; ++mt)
                    #pragma unroll
                    for (int nt = 0; nt < 4; ++nt)
                        mma_bf16(acc[mt][nt], al[mt], bf[0][nt]);  // lo*hi
                #pragma unroll
                for (int mt = 0; mt < 4; ++mt)
                    #pragma unroll
                    for (int nt = 0; nt < 4; ++nt)
                        mma_bf16(acc[mt][nt], ah[mt], bf[1][nt]);  // hi*lo
            }
        }
        __syncthreads();   // all MMA reads of A done before D overwrites A

        // ---- stage acc into D (aliases dead A rows) --------------------------
        #pragma unroll
        for (int mt = 0; mt < 4; ++mt)
            #pragma unroll
            for (int nt = 0; nt < 4; ++nt) {
                int m0 = (mg << 6) + (mt << 4), nn = n0w + (nt << 3) + cc;
                *(float2*)(Dst + (m0 + g) * DROW + nn) =
                    make_float2(acc[mt][nt][0], acc[mt][nt][1]);
                *(float2*)(Dst + (m0 + g + 8) * DROW + nn) =
                    make_float2(acc[mt][nt][2], acc[mt][nt][3]);
            }
        __syncthreads();

        // ---- activation epilogue --------------------------------------------
        const int sg2 = tid >> 8;          // sample group 0/1
        const int nn  = tid & 255;
        if (L == 0) {
            // in-place D -> new A exchange, batched 4 samples per barrier
            float bn = b2[nn];
            #pragma unroll 1
            for (int bb = 0; bb < 3; ++bb) {
                float t5[4][5];
                #pragma unroll
                for (int j = 0; j < 4; ++j) {
                    int mr = (sg2 * 12 + bb * 4 + j) * 5;
                    #pragma unroll
                    for (int c = 0; c < 5; ++c)
                        t5[j][c] = Dst[(mr + c) * DROW + nn];
                }
                __syncthreads();           // all reads of these rows done
                #pragma unroll
                for (int j = 0; j < 4; ++j) {
                    int mr = (sg2 * 12 + bb * 4 + j) * 5;
                    float yv = ftanh(t5[j][0] + bn);
                    float sgm = fmaf(-yv, yv, 1.0f);
                    float gq = CX * t5[j][1] * t5[j][1] +
                               CY * t5[j][2] * t5[j][2] +
                               CZ * t5[j][3] * t5[j][3];
                    storeA(mr + 0, nn, yv);
                    storeA(mr + 1, nn, sgm * t5[j][1]);
                    storeA(mr + 2, nn, sgm * t5[j][2]);
                    storeA(mr + 3, nn, sgm * t5[j][3]);
                    storeA(mr + 4, nn, fmaf(sgm, t5[j][4],
                                            -2.0f * yv * sgm * gq));
                }
            }
            __syncthreads();
        } else {
            float bn  = b3[nn];
            float w40 = W4[nn], w41 = W4[HD + nn];
            #pragma unroll 1
            for (int s12 = 0; s12 < 12; ++s12) {
                int s = sg2 * 12 + s12, mr = s * 5;
                float u  = Dst[(mr + 0) * DROW + nn] + bn;
                float tx = Dst[(mr + 1) * DROW + nn];
                float ty = Dst[(mr + 2) * DROW + nn];
                float tz = Dst[(mr + 3) * DROW + nn];
                float qa = Dst[(mr + 4) * DROW + nn];
                float yv = ftanh(u);
                float sgm = fmaf(-yv, yv, 1.0f);
                float gq = CX * tx * tx + CY * ty * ty + CZ * tz * tz;
                float qn = fmaf(sgm, qa, -2.0f * yv * sgm * gq);
                float v0 = w40 * yv, v1 = w41 * yv;
                float v2 = w40 * qn, v3 = w41 * qn;
                #pragma unroll
                for (int o = 16; o; o >>= 1) {
                    v0 += __shfl_xor_sync(0xFFFFFFFFu, v0, o);
                    v1 += __shfl_xor_sync(0xFFFFFFFFu, v1, o);
                    v2 += __shfl_xor_sync(0xFFFFFFFFu, v2, o);
                    v3 += __shfl_xor_sync(0xFFFFFFFFu, v3, o);
                }
                if (lid == 0) {
                    float* pp = part + (s * 8 + (wid & 7)) * 4;
                    pp[0] = v0; pp[1] = v1; pp[2] = v2; pp[3] = v3;
                }
            }
            __syncthreads();
        }
    }

    // ---- residual output -----------------------------------------------------
    if (tid < SB) {
        int n = n0 + tid;
        if (n < N) {
            float P0 = 0.f, P1 = 0.f, Q0 = 0.f, Q1 = 0.f;
            #pragma unroll
            for (int w = 0; w < 8; ++w) {
                const float* pp = part + (tid * 8 + w) * 4;
                P0 += pp[0]; P1 += pp[1]; Q0 += pp[2]; Q1 += pp[3];
            }
            P0 += b4[0]; P1 += b4[1];
            float fs = xyzf[tid * 4 + 3];
            float kw = 6.283185307179586f * fmaf(fs, 500.0f, 100.0f) / 343.0f;
            float kx = 0.21f * kw;
            float K2 = kx * kx;
            out[n]     = 2.0f * Q0 + K2 * fmaf(2.0f, P0, 0.1f);
            out[N + n] = 1.5f * Q1 + K2 * fmaf(1.5f, P1, -0.05f);
        }
    }
}

extern "C" void kernel_launch(void* const* d_in, const int* in_sizes, int n_in,
                              void* d_out, int out_size)
{
    const float* x  = (const float*)d_in[0];
    const float* y  = (const float*)d_in[1];
    const float* z  = (const float*)d_in[2];
    const float* f  = (const float*)d_in[3];
    const float* W1 = (const float*)d_in[4];
    const float* b1 = (const float*)d_in[5];
    const float* W2 = (const float*)d_in[6];
    const float* b2 = (const float*)d_in[7];
    const float* W3 = (const float*)d_in[8];
    const float* b3 = (const float*)d_in[9];
    const float* W4 = (const float*)d_in[10];
    const float* b4 = (const float*)d_in[11];
    float* out = (float*)d_out;

    int N = in_sizes[0];
    prep_weights<<<512, 256>>>(W2, W3);

    cudaFuncSetAttribute(bvp_mma_kernel,
                         cudaFuncAttributeMaxDynamicSharedMemorySize,
                         SMEM_BYTES);
    int blocks = (N + SB - 1) / SB;
    bvp_mma_kernel<<<blocks, 512, SMEM_BYTES>>>(x, y, z, f, W1, b1, b2, b3,
                                                W4, b4, out, N);
}

// round 10
// speedup vs baseline: 1.1854x; 1.1854x over previous
#include <cuda_runtime.h>
#include <cuda_bf16.h>
#include <cstdint>

// ---------------------------------------------------------------------------
// BVP Helmholtz residual via 2nd-order jet propagation on mma.sync bf16 HMMA
// (3-pass hi/lo split). Round 10 = round 8 geometry (512 thr, M=128, SB=24)
// with the CTA-wide mainloop barriers replaced by PER-PAIR B pipelines:
// each of 8 warp pairs (mg0,mg1; same n-slice) owns a private B slice buffer,
// mg0 runs its own cp.async pipeline, pair syncs via named barrier (64 thr).
// Warp pairs drift independently -> tensor-pipe gaps of one pair are filled
// by others. Full barriers remain only around the A-exchange epilogues.
// ---------------------------------------------------------------------------

#define HD 256
#define SB 24          // samples per CTA
#define AROW 1040      // A row bytes: hi[0,512) pad lo[528,1040)  == D row
#define BROW 80        // B slice row stride bytes
#define BSLICE_SPLIT 2560   // 32 rows * 80
#define BSLICE 5120         // 2 splits
#define BSTAGE 40960        // 8 slices
#define DROW 260       // D row stride in floats (= 1040 B)

#define A_OFF 0
#define B_OFF 133120   // 128*1040
#define XYZF_OFF 215040
#define PART_OFF 215424
#define SMEM_BYTES 218624

// prepped weights: [layer][split hi/lo][n][k] bf16
__device__ __align__(16) __nv_bfloat16 Wbf[2][2][HD][HD];

__global__ __launch_bounds__(256)
void prep_weights(const float* __restrict__ W2, const float* __restrict__ W3)
{
    int t = blockIdx.x * 256 + threadIdx.x;      // 131072
    int layer = t >> 16, n = (t >> 8) & 255, k = t & 255;
    float w = (layer ? W3 : W2)[n * HD + k];
    __nv_bfloat16 h = __float2bfloat16(w);
    __nv_bfloat16 l = __float2bfloat16(w - __bfloat162float(h));
    Wbf[layer][0][n][k] = h;
    Wbf[layer][1][n][k] = l;
}

__device__ __forceinline__ uint32_t smem_u32(const void* p) {
    uint32_t a;
    asm("{ .reg .u64 t; cvta.to.shared.u64 t, %1; cvt.u32.u64 %0, t; }"
        : "=r"(a) : "l"(p));
    return a;
}
__device__ __forceinline__ void ldsm4(uint32_t* r, uint32_t a) {
    asm volatile("ldmatrix.sync.aligned.m8n8.x4.shared.b16 {%0,%1,%2,%3}, [%4];"
                 : "=r"(r[0]), "=r"(r[1]), "=r"(r[2]), "=r"(r[3]) : "r"(a));
}
__device__ __forceinline__ void ldsm2(uint32_t* r, uint32_t a) {
    asm volatile("ldmatrix.sync.aligned.m8n8.x2.shared.b16 {%0,%1}, [%2];"
                 : "=r"(r[0]), "=r"(r[1]) : "r"(a));
}
__device__ __forceinline__ void mma_bf16(float* c, const uint32_t* a,
                                         const uint32_t* b) {
    asm volatile("mma.sync.aligned.m16n8k16.row.col.f32.bf16.bf16.f32 "
                 "{%0,%1,%2,%3}, {%4,%5,%6,%7}, {%8,%9}, {%0,%1,%2,%3};"
                 : "+f"(c[0]), "+f"(c[1]), "+f"(c[2]), "+f"(c[3])
                 : "r"(a[0]), "r"(a[1]), "r"(a[2]), "r"(a[3]),
                   "r"(b[0]), "r"(b[1]));
}
__device__ __forceinline__ void cp16(uint32_t sa, const void* ga) {
    asm volatile("cp.async.cg.shared.global [%0], [%1], 16;"
                 :: "r"(sa), "l"(__cvta_generic_to_global(ga)) : "memory");
}
#define CP_COMMIT() asm volatile("cp.async.commit_group;" ::: "memory")
#define CP_WAIT(n)  asm volatile("cp.async.wait_group %0;" :: "n"(n) : "memory")
#define PAIR_BAR(id) asm volatile("bar.sync %0, 64;" :: "r"(id) : "memory")

// fast tanh: 1 - 2/(exp(2u)+1). abs err ~3e-7.
__device__ __forceinline__ float ftanh(float u) {
    float e = __expf(2.0f * u);
    return 1.0f - __fdividef(2.0f, e + 1.0f);
}

__global__ __launch_bounds__(512, 1)
void bvp_mma_kernel(const float* __restrict__ gx, const float* __restrict__ gy,
                    const float* __restrict__ gz, const float* __restrict__ gf,
                    const float* __restrict__ W1, const float* __restrict__ b1,
                    const float* __restrict__ b2, const float* __restrict__ b3,
                    const float* __restrict__ W4, const float* __restrict__ b4,
                    float* __restrict__ out, int N)
{
    extern __shared__ char sm[];
    const uint32_t smb = smem_u32(sm);
    float* Dst  = (float*)(sm + A_OFF);       // aliases A region, row-for-row
    float* xyzf = (float*)(sm + XYZF_OFF);
    float* part = (float*)(sm + PART_OFF);    // [24][8][4]

    const int tid = threadIdx.x;
    const int wid = tid >> 5;
    const int lid = tid & 31;
    const int mg  = wid >> 3;                 // m-group 0/1 (rows mg*64..+64)
    const int ng  = wid & 7;                  // n-slice (cols ng*32..+32)
    const int n0w = ng << 5;
    const int n0  = blockIdx.x * SB;

    const float CX = (float)((0.5 * 0.6) * (0.5 * 0.6));
    const float CY = (float)((0.7 * 0.6) * (0.7 * 0.6));
    const float CZ = (float)((0.7 * 0.5) * (0.7 * 0.5));

    // per-pair slice stage: mg0 warp copies its pair's 32 B rows (both splits)
    const uint32_t bslice_base = smb + B_OFF + ng * BSLICE;
    auto issue_slice = [&](int L, int kc, int buf) {
        #pragma unroll
        for (int j = 0; j < 8; ++j) {
            int idx = lid + (j << 5);            // 0..255
            int split = idx >> 7;
            int rem = idx & 127;
            int rr = rem >> 2, seg = rem & 3;
            uint32_t sa = bslice_base + buf * BSTAGE + split * BSLICE_SPLIT +
                          rr * BROW + seg * 16;
            cp16(sa, &Wbf[L][split][n0w + rr][kc * 32 + seg * 8]);
        }
        CP_COMMIT();
    };

    auto storeA = [&](int m, int k, float v) {
        __nv_bfloat16 h = __float2bfloat16(v);
        __nv_bfloat16 l = __float2bfloat16(v - __bfloat162float(h));
        char* base = sm + A_OFF + m * AROW + k * 2;
        *(__nv_bfloat16*)(base)       = h;
        *(__nv_bfloat16*)(base + 528) = l;
    };

    // prefetch first B stage of layer 0 (per pair, mg0 only)
    if (mg == 0) issue_slice(0, 0, 0);

    // coords
    if (tid < 96) {
        int ss = tid >> 2, w = tid & 3;
        int n = n0 + ss; if (n >= N) n = N - 1;
        const float* p = (w == 0) ? gx : (w == 1) ? gy : (w == 2) ? gz : gf;
        xyzf[tid] = p[n];
    }
    __syncthreads();

    // ---- layer 1: 4 -> 256, jets analytically ------------------------------
    #pragma unroll 1
    for (int it = 0; it < 12; ++it) {
        int idx = tid + (it << 9);               // 24*256 = 6144 items
        int s = idx >> 8, k = idx & 255;
        float4 w = *(const float4*)(W1 + k * 4);
        float u = fmaf(w.x, xyzf[s * 4 + 0], fmaf(w.y, xyzf[s * 4 + 1],
                  fmaf(w.z, xyzf[s * 4 + 2], fmaf(w.w, xyzf[s * 4 + 3],
                  b1[k]))));
        float yv = ftanh(u);
        float sg = fmaf(-yv, yv, 1.0f);
        float g  = CX * w.x * w.x + CY * w.y * w.y + CZ * w.z * w.z;
        int m = s * 5;
        storeA(m + 0, k, yv);
        storeA(m + 1, k, sg * w.x);
        storeA(m + 2, k, sg * w.y);
        storeA(m + 3, k, sg * w.z);
        storeA(m + 4, k, -2.0f * yv * sg * g);
    }

    const int g = lid >> 2, cc = (lid & 3) << 1;

    // ---- hidden layers 2,3 --------------------------------------------------
    #pragma unroll 1
    for (int L = 0; L < 2; ++L) {
        if (L == 0) __syncthreads();   // A (layer1) visible to all
        float acc[4][4][4];
        #pragma unroll
        for (int mt = 0; mt < 4; ++mt)
            #pragma unroll
            for (int nt = 0; nt < 4; ++nt)
                #pragma unroll
                for (int r = 0; r < 4; ++r) acc[mt][nt][r] = 0.f;

        #pragma unroll 1
        for (int kc = 0; kc < 8; ++kc) {
            int gi = L * 8 + kc;
            // pair-private pipeline sync: mg0 lands the data, pair barrier
            // also proves both warps finished chunk gi-1 (buffer (gi+1)&1)
            if (mg == 0) CP_WAIT(0);
            PAIR_BAR(ng + 1);
            if (mg == 0 && gi + 1 < 16)
                issue_slice((gi + 1) >> 3, (gi + 1) & 7, (gi + 1) & 1);

            int buf = gi & 1;
            #pragma unroll
            for (int ks = 0; ks < 2; ++ks) {
                int kl0 = ks << 4;
                uint32_t bf[2][4][2];
                #pragma unroll
                for (int nt = 0; nt < 4; ++nt) {
                    uint32_t ba = bslice_base + buf * BSTAGE +
                                  ((nt << 3) + (lid & 7)) * BROW +
                                  (kl0 + (lid & 8)) * 2;
                    ldsm2(bf[0][nt], ba);
                    ldsm2(bf[1][nt], ba + BSLICE_SPLIT);
                }
                #pragma unroll
                for (int mt = 0; mt < 4; ++mt) {
                    int row = (mg << 6) + (mt << 4) + (lid & 15);
                    uint32_t aa = smb + A_OFF + row * AROW +
                                  (kc * 32 + kl0 + ((lid >> 4) << 3)) * 2;
                    uint32_t ah[4], al[4];
                    ldsm4(ah, aa);
                    ldsm4(al, aa + 528);
                    #pragma unroll
                    for (int nt = 0; nt < 4; ++nt) {
                        mma_bf16(acc[mt][nt], ah, bf[0][nt]);  // hi*hi
                        mma_bf16(acc[mt][nt], al, bf[0][nt]);  // lo*hi
                        mma_bf16(acc[mt][nt], ah, bf[1][nt]);  // hi*lo
                    }
                }
            }
        }
        __syncthreads();   // all MMA reads of A done before D overwrites A

        // ---- stage acc into D (aliases dead A rows) --------------------------
        #pragma unroll
        for (int mt = 0; mt < 4; ++mt)
            #pragma unroll
            for (int nt = 0; nt < 4; ++nt) {
                int m0 = (mg << 6) + (mt << 4), nn = n0w + (nt << 3) + cc;
                *(float2*)(Dst + (m0 + g) * DROW + nn) =
                    make_float2(acc[mt][nt][0], acc[mt][nt][1]);
                *(float2*)(Dst + (m0 + g + 8) * DROW + nn) =
                    make_float2(acc[mt][nt][2], acc[mt][nt][3]);
            }
        __syncthreads();

        // ---- activation epilogue --------------------------------------------
        const int sg2 = tid >> 8;          // sample group 0/1
        const int nn  = tid & 255;
        if (L == 0) {
            // in-place D -> new A exchange, batched 4 samples per barrier
            float bn = b2[nn];
            #pragma unroll 1
            for (int bb = 0; bb < 3; ++bb) {
                float t5[4][5];
                #pragma unroll
                for (int j = 0; j < 4; ++j) {
                    int mr = (sg2 * 12 + bb * 4 + j) * 5;
                    #pragma unroll
                    for (int c = 0; c < 5; ++c)
                        t5[j][c] = Dst[(mr + c) * DROW + nn];
                }
                __syncthreads();           // all reads of these rows done
                #pragma unroll
                for (int j = 0; j < 4; ++j) {
                    int mr = (sg2 * 12 + bb * 4 + j) * 5;
                    float yv = ftanh(t5[j][0] + bn);
                    float sgm = fmaf(-yv, yv, 1.0f);
                    float gq = CX * t5[j][1] * t5[j][1] +
                               CY * t5[j][2] * t5[j][2] +
                               CZ * t5[j][3] * t5[j][3];
                    storeA(mr + 0, nn, yv);
                    storeA(mr + 1, nn, sgm * t5[j][1]);
                    storeA(mr + 2, nn, sgm * t5[j][2]);
                    storeA(mr + 3, nn, sgm * t5[j][3]);
                    storeA(mr + 4, nn, fmaf(sgm, t5[j][4],
                                            -2.0f * yv * sgm * gq));
                }
            }
            __syncthreads();
        } else {
            float bn  = b3[nn];
            float w40 = W4[nn], w41 = W4[HD + nn];
            #pragma unroll 1
            for (int s12 = 0; s12 < 12; ++s12) {
                int s = sg2 * 12 + s12, mr = s * 5;
                float u  = Dst[(mr + 0) * DROW + nn] + bn;
                float tx = Dst[(mr + 1) * DROW + nn];
                float ty = Dst[(mr + 2) * DROW + nn];
                float tz = Dst[(mr + 3) * DROW + nn];
                float qa = Dst[(mr + 4) * DROW + nn];
                float yv = ftanh(u);
                float sgm = fmaf(-yv, yv, 1.0f);
                float gq = CX * tx * tx + CY * ty * ty + CZ * tz * tz;
                float qn = fmaf(sgm, qa, -2.0f * yv * sgm * gq);
                float v0 = w40 * yv, v1 = w41 * yv;
                float v2 = w40 * qn, v3 = w41 * qn;
                #pragma unroll
                for (int o = 16; o; o >>= 1) {
                    v0 += __shfl_xor_sync(0xFFFFFFFFu, v0, o);
                    v1 += __shfl_xor_sync(0xFFFFFFFFu, v1, o);
                    v2 += __shfl_xor_sync(0xFFFFFFFFu, v2, o);
                    v3 += __shfl_xor_sync(0xFFFFFFFFu, v3, o);
                }
                if (lid == 0) {
                    float* pp = part + (s * 8 + (wid & 7)) * 4;
                    pp[0] = v0; pp[1] = v1; pp[2] = v2; pp[3] = v3;
                }
            }
            __syncthreads();
        }
    }

    // ---- residual output -----------------------------------------------------
    if (tid < SB) {
        int n = n0 + tid;
        if (n < N) {
            float P0 = 0.f, P1 = 0.f, Q0 = 0.f, Q1 = 0.f;
            #pragma unroll
            for (int w = 0; w < 8; ++w) {
                const float* pp = part + (tid * 8 + w) * 4;
                P0 += pp[0]; P1 += pp[1]; Q0 += pp[2]; Q1 += pp[3];
            }
            P0 += b4[0]; P1 += b4[1];
            float fs = xyzf[tid * 4 + 3];
            float kw = 6.283185307179586f * fmaf(fs, 500.0f, 100.0f) / 343.0f;
            float kx = 0.21f * kw;
            float K2 = kx * kx;
            out[n]     = 2.0f * Q0 + K2 * fmaf(2.0f, P0, 0.1f);
            out[N + n] = 1.5f * Q1 + K2 * fmaf(1.5f, P1, -0.05f);
        }
    }
}

extern "C" void kernel_launch(void* const* d_in, const int* in_sizes, int n_in,
                              void* d_out, int out_size)
{
    const float* x  = (const float*)d_in[0];
    const float* y  = (const float*)d_in[1];
    const float* z  = (const float*)d_in[2];
    const float* f  = (const float*)d_in[3];
    const float* W1 = (const float*)d_in[4];
    const float* b1 = (const float*)d_in[5];
    const float* W2 = (const float*)d_in[6];
    const float* b2 = (const float*)d_in[7];
    const float* W3 = (const float*)d_in[8];
    const float* b3 = (const float*)d_in[9];
    const float* W4 = (const float*)d_in[10];
    const float* b4 = (const float*)d_in[11];
    float* out = (float*)d_out;

    int N = in_sizes[0];
    prep_weights<<<512, 256>>>(W2, W3);

    cudaFuncSetAttribute(bvp_mma_kernel,
                         cudaFuncAttributeMaxDynamicSharedMemorySize,
                         SMEM_BYTES);
    int blocks = (N + SB - 1) / SB;
    bvp_mma_kernel<<<blocks, 512, SMEM_BYTES>>>(x, y, z, f, W1, b1, b2, b3,
                                                W4, b4, out, N);
}